// round 4
// baseline (speedup 1.0000x reference)
#include <cuda_runtime.h>

// Scratch accumulators — zero at module load; the LAST block of every launch
// resets them, so every graph replay starts from zero. No allocation.
__device__ double g_S[32];
__device__ double g_sq;
__device__ unsigned int g_count;

#define GRID_BLOCKS 1184
#define BLOCK_THREADS 256

__global__ void __launch_bounds__(BLOCK_THREADS, 8) fused_loss_kernel(
    const float* __restrict__ data,
    const float* __restrict__ pred,
    long long total4,            // number of float4 elements = N*D/4
    float* __restrict__ out)
{
    const int tid = threadIdx.x;
    const int colgrp = tid & 7;                 // which float4 within a 32-col row
    const float4 p4 = reinterpret_cast<const float4*>(pred)[colgrp];
    const float4* __restrict__ d4 = reinterpret_cast<const float4*>(data);

    float s0 = 0.f, s1 = 0.f, s2 = 0.f, s3 = 0.f;
    float sq = 0.f;

    long long idx = (long long)blockIdx.x * BLOCK_THREADS + tid;
    const long long stride = (long long)GRID_BLOCKS * BLOCK_THREADS;  // multiple of 8

    // Main loop: 4 independent streaming loads in flight per iteration.
    while (idx + 3 * stride < total4) {
        float4 v0 = __ldcs(&d4[idx]);
        float4 v1 = __ldcs(&d4[idx + stride]);
        float4 v2 = __ldcs(&d4[idx + 2 * stride]);
        float4 v3 = __ldcs(&d4[idx + 3 * stride]);
        idx += 4 * stride;

        float a0 = v0.x - p4.x, a1 = v0.y - p4.y, a2 = v0.z - p4.z, a3 = v0.w - p4.w;
        float b0 = v1.x - p4.x, b1 = v1.y - p4.y, b2 = v1.z - p4.z, b3 = v1.w - p4.w;
        float c0 = v2.x - p4.x, c1 = v2.y - p4.y, c2 = v2.z - p4.z, c3 = v2.w - p4.w;
        float e0 = v3.x - p4.x, e1 = v3.y - p4.y, e2 = v3.z - p4.z, e3 = v3.w - p4.w;

        s0 += a0 + b0 + c0 + e0;
        s1 += a1 + b1 + c1 + e1;
        s2 += a2 + b2 + c2 + e2;
        s3 += a3 + b3 + c3 + e3;

        sq = fmaf(a0, a0, sq); sq = fmaf(a1, a1, sq);
        sq = fmaf(a2, a2, sq); sq = fmaf(a3, a3, sq);
        sq = fmaf(b0, b0, sq); sq = fmaf(b1, b1, sq);
        sq = fmaf(b2, b2, sq); sq = fmaf(b3, b3, sq);
        sq = fmaf(c0, c0, sq); sq = fmaf(c1, c1, sq);
        sq = fmaf(c2, c2, sq); sq = fmaf(c3, c3, sq);
        sq = fmaf(e0, e0, sq); sq = fmaf(e1, e1, sq);
        sq = fmaf(e2, e2, sq); sq = fmaf(e3, e3, sq);
    }
    // Tail
    for (; idx < total4; idx += stride) {
        float4 v = __ldcs(&d4[idx]);
        float d0 = v.x - p4.x, d1 = v.y - p4.y, d2 = v.z - p4.z, d3 = v.w - p4.w;
        s0 += d0; s1 += d1; s2 += d2; s3 += d3;
        sq = fmaf(d0, d0, sq); sq = fmaf(d1, d1, sq);
        sq = fmaf(d2, d2, sq); sq = fmaf(d3, d3, sq);
    }

    // Warp reduce: lanes {l, l+8, l+16, l+24} share the same columns.
    const unsigned full = 0xFFFFFFFFu;
    s0 += __shfl_xor_sync(full, s0, 8);
    s1 += __shfl_xor_sync(full, s1, 8);
    s2 += __shfl_xor_sync(full, s2, 8);
    s3 += __shfl_xor_sync(full, s3, 8);
    s0 += __shfl_xor_sync(full, s0, 16);
    s1 += __shfl_xor_sync(full, s1, 16);
    s2 += __shfl_xor_sync(full, s2, 16);
    s3 += __shfl_xor_sync(full, s3, 16);
    sq += __shfl_xor_sync(full, sq, 16);
    sq += __shfl_xor_sync(full, sq, 8);
    sq += __shfl_xor_sync(full, sq, 4);
    sq += __shfl_xor_sync(full, sq, 2);
    sq += __shfl_xor_sync(full, sq, 1);

    __shared__ float sS[8][8][4];   // [warp][colgrp][component]
    __shared__ float sSq[8];
    __shared__ bool isLast;
    const int warp = tid >> 5;
    const int lane = tid & 31;
    if (lane < 8) {
        sS[warp][lane][0] = s0;
        sS[warp][lane][1] = s1;
        sS[warp][lane][2] = s2;
        sS[warp][lane][3] = s3;
    }
    if (lane == 0) sSq[warp] = sq;
    __syncthreads();

    if (tid < 32) {
        const int g = tid >> 2;      // colgrp 0..7
        const int k = tid & 3;       // component 0..3
        float acc = 0.f;
        #pragma unroll
        for (int w = 0; w < 8; w++) acc += sS[w][g][k];
        atomicAdd(&g_S[g * 4 + k], (double)acc);
    }
    if (tid == 32) {
        float acc = 0.f;
        #pragma unroll
        for (int w = 0; w < 8; w++) acc += sSq[w];
        atomicAdd(&g_sq, (double)acc);
    }

    // Signal completion; last block finalizes + resets accumulators.
    __threadfence();
    __syncthreads();
    if (tid == 0) {
        unsigned int done = atomicAdd(&g_count, 1u);
        isLast = (done == (unsigned int)(GRID_BLOCKS - 1));
    }
    __syncthreads();

    if (isLast && tid < 32) {
        __threadfence();  // acquire: every lane fences before reading totals
        double s = g_S[tid];
        double q = g_sq;
        double v = s * s;
        v += __shfl_xor_sync(full, v, 16);
        v += __shfl_xor_sync(full, v, 8);
        v += __shfl_xor_sync(full, v, 4);
        v += __shfl_xor_sync(full, v, 2);
        v += __shfl_xor_sync(full, v, 1);
        if (tid == 0) {
            out[0] = (float)((v - q) / 32.0);
            g_sq = 0.0;
            g_count = 0u;
        }
        g_S[tid] = 0.0;
    }
}

extern "C" void kernel_launch(void* const* d_in, const int* in_sizes, int n_in,
                              void* d_out, int out_size) {
    const float* data = (const float*)d_in[0];   // output: [N, 32] fp32
    const float* pred = (const float*)d_in[1];   // pred_avg: [32] fp32
    long long total4 = (long long)in_sizes[0] / 4;

    fused_loss_kernel<<<GRID_BLOCKS, BLOCK_THREADS>>>(data, pred, total4, (float*)d_out);
}

// round 5
// speedup vs baseline: 1.1257x; 1.1257x over previous
#include <cuda_runtime.h>

// Scratch accumulators — zero at module load; the LAST block of every launch
// resets them, so every graph replay starts from zero. No allocation.
__device__ double g_S[32];
__device__ double g_sq;
__device__ unsigned int g_count;

#define GRID_BLOCKS 296          // 2 CTAs per SM (148 SMs): oe*MLP_p1 = 8 < Q_th
#define BLOCK_THREADS 1024       // 32 warps/block -> 64 warps/SM, same as before
#define NWARPS (BLOCK_THREADS / 32)

__global__ void __launch_bounds__(BLOCK_THREADS, 2) fused_loss_kernel(
    const float* __restrict__ data,
    const float* __restrict__ pred,
    long long total4,            // number of float4 elements = N*D/4
    float* __restrict__ out)
{
    const int tid = threadIdx.x;
    const int colgrp = tid & 7;                 // which float4 within a 32-col row
    const float4 p4 = reinterpret_cast<const float4*>(pred)[colgrp];
    const float4* __restrict__ d4 = reinterpret_cast<const float4*>(data);

    float s0 = 0.f, s1 = 0.f, s2 = 0.f, s3 = 0.f;
    float sq = 0.f;

    long long idx = (long long)blockIdx.x * BLOCK_THREADS + tid;
    const long long stride = (long long)GRID_BLOCKS * BLOCK_THREADS;  // multiple of 8

    // Main loop: 4 independent streaming loads in flight per iteration.
    while (idx + 3 * stride < total4) {
        float4 v0 = __ldcs(&d4[idx]);
        float4 v1 = __ldcs(&d4[idx + stride]);
        float4 v2 = __ldcs(&d4[idx + 2 * stride]);
        float4 v3 = __ldcs(&d4[idx + 3 * stride]);
        idx += 4 * stride;

        float a0 = v0.x - p4.x, a1 = v0.y - p4.y, a2 = v0.z - p4.z, a3 = v0.w - p4.w;
        float b0 = v1.x - p4.x, b1 = v1.y - p4.y, b2 = v1.z - p4.z, b3 = v1.w - p4.w;
        float c0 = v2.x - p4.x, c1 = v2.y - p4.y, c2 = v2.z - p4.z, c3 = v2.w - p4.w;
        float e0 = v3.x - p4.x, e1 = v3.y - p4.y, e2 = v3.z - p4.z, e3 = v3.w - p4.w;

        s0 += a0 + b0 + c0 + e0;
        s1 += a1 + b1 + c1 + e1;
        s2 += a2 + b2 + c2 + e2;
        s3 += a3 + b3 + c3 + e3;

        sq = fmaf(a0, a0, sq); sq = fmaf(a1, a1, sq);
        sq = fmaf(a2, a2, sq); sq = fmaf(a3, a3, sq);
        sq = fmaf(b0, b0, sq); sq = fmaf(b1, b1, sq);
        sq = fmaf(b2, b2, sq); sq = fmaf(b3, b3, sq);
        sq = fmaf(c0, c0, sq); sq = fmaf(c1, c1, sq);
        sq = fmaf(c2, c2, sq); sq = fmaf(c3, c3, sq);
        sq = fmaf(e0, e0, sq); sq = fmaf(e1, e1, sq);
        sq = fmaf(e2, e2, sq); sq = fmaf(e3, e3, sq);
    }
    // Tail
    for (; idx < total4; idx += stride) {
        float4 v = __ldcs(&d4[idx]);
        float d0 = v.x - p4.x, d1 = v.y - p4.y, d2 = v.z - p4.z, d3 = v.w - p4.w;
        s0 += d0; s1 += d1; s2 += d2; s3 += d3;
        sq = fmaf(d0, d0, sq); sq = fmaf(d1, d1, sq);
        sq = fmaf(d2, d2, sq); sq = fmaf(d3, d3, sq);
    }

    // Warp reduce: lanes {l, l+8, l+16, l+24} share the same columns.
    const unsigned full = 0xFFFFFFFFu;
    s0 += __shfl_xor_sync(full, s0, 8);
    s1 += __shfl_xor_sync(full, s1, 8);
    s2 += __shfl_xor_sync(full, s2, 8);
    s3 += __shfl_xor_sync(full, s3, 8);
    s0 += __shfl_xor_sync(full, s0, 16);
    s1 += __shfl_xor_sync(full, s1, 16);
    s2 += __shfl_xor_sync(full, s2, 16);
    s3 += __shfl_xor_sync(full, s3, 16);
    sq += __shfl_xor_sync(full, sq, 16);
    sq += __shfl_xor_sync(full, sq, 8);
    sq += __shfl_xor_sync(full, sq, 4);
    sq += __shfl_xor_sync(full, sq, 2);
    sq += __shfl_xor_sync(full, sq, 1);

    __shared__ float sS[NWARPS][8][4];   // [warp][colgrp][component]
    __shared__ float sSq[NWARPS];
    __shared__ bool isLast;
    const int warp = tid >> 5;
    const int lane = tid & 31;
    if (lane < 8) {
        sS[warp][lane][0] = s0;
        sS[warp][lane][1] = s1;
        sS[warp][lane][2] = s2;
        sS[warp][lane][3] = s3;
    }
    if (lane == 0) sSq[warp] = sq;
    __syncthreads();

    if (tid < 32) {
        const int g = tid >> 2;      // colgrp 0..7
        const int k = tid & 3;       // component 0..3
        float acc = 0.f;
        #pragma unroll
        for (int w = 0; w < NWARPS; w++) acc += sS[w][g][k];
        atomicAdd(&g_S[g * 4 + k], (double)acc);
    }
    if (tid == 32) {
        float acc = 0.f;
        #pragma unroll
        for (int w = 0; w < NWARPS; w++) acc += sSq[w];
        atomicAdd(&g_sq, (double)acc);
    }

    // Signal completion; last block finalizes + resets accumulators.
    __threadfence();
    __syncthreads();
    if (tid == 0) {
        unsigned int done = atomicAdd(&g_count, 1u);
        isLast = (done == (unsigned int)(GRID_BLOCKS - 1));
    }
    __syncthreads();

    if (isLast && tid < 32) {
        __threadfence();  // acquire: every lane fences before reading totals
        double s = g_S[tid];
        double q = g_sq;
        double v = s * s;
        v += __shfl_xor_sync(full, v, 16);
        v += __shfl_xor_sync(full, v, 8);
        v += __shfl_xor_sync(full, v, 4);
        v += __shfl_xor_sync(full, v, 2);
        v += __shfl_xor_sync(full, v, 1);
        if (tid == 0) {
            out[0] = (float)((v - q) / 32.0);
            g_sq = 0.0;
            g_count = 0u;
        }
        g_S[tid] = 0.0;
    }
}

extern "C" void kernel_launch(void* const* d_in, const int* in_sizes, int n_in,
                              void* d_out, int out_size) {
    const float* data = (const float*)d_in[0];   // output: [N, 32] fp32
    const float* pred = (const float*)d_in[1];   // pred_avg: [32] fp32
    long long total4 = (long long)in_sizes[0] / 4;

    fused_loss_kernel<<<GRID_BLOCKS, BLOCK_THREADS>>>(data, pred, total4, (float*)d_out);
}